// round 9
// baseline (speedup 1.0000x reference)
#include <cuda_runtime.h>
#include <cuda_bf16.h>
#include <math.h>

#define BB 4096
#define SS 512
#define EE 64
#define MM 16
#define OUTD 64
#define NSTEPS 5

// Scratch: memories transposed per batch: g_memT[b*MM*SS + m*SS + s]
__device__ float g_memT[(size_t)BB * MM * SS];
// Pre-transposed small weights (k-major) for the recurrence phase
__device__ float g_whhT[32 * 128];   // [k][j]
__device__ float g_pwT [32 * 16];    // [k][m]
__device__ float g_w1T [32 * 32];    // [k][j]
__device__ float g_w2T [32 * 32];    // [k][j]
__device__ float g_w3T [32 * 64];    // [k][j]
__device__ float g_bsum[128];        // bih + bhh
// Precomputed bf16 B-fragments for the reading MLP (hi/lo split)
__device__ uint2 g_frags[56 * 32];

// ---------------- bf16 pack/split helpers ----------------
__device__ __forceinline__ unsigned int packbf(float lo, float hi) {
    __nv_bfloat162 p = __floats2bfloat162_rn(lo, hi);   // .x -> low 16 bits
    return *reinterpret_cast<unsigned int*>(&p);
}
__device__ __forceinline__ void split2(float v0, float v1,
                                       unsigned int& ph, unsigned int& pl) {
    ph = packbf(v0, v1);
    float f0 = __uint_as_float(ph << 16);
    float f1 = __uint_as_float(ph & 0xffff0000u);
    pl = packbf(v0 - f0, v1 - f1);
}

__device__ __forceinline__ void mma16816(float* c, const unsigned int* a, uint2 b) {
    asm("mma.sync.aligned.m16n8k16.row.col.f32.bf16.bf16.f32 "
        "{%0,%1,%2,%3}, {%4,%5,%6,%7}, {%8,%9}, {%0,%1,%2,%3};"
        : "+f"(c[0]), "+f"(c[1]), "+f"(c[2]), "+f"(c[3])
        : "r"(a[0]), "r"(a[1]), "r"(a[2]), "r"(a[3]), "r"(b.x), "r"(b.y));
}

// ---------------------------------------------------------------------------
// Kernel 0: weight transposes + B-fragment construction
// ---------------------------------------------------------------------------
__device__ __forceinline__ uint2 make_bfrag(const float* __restrict__ w,
                                            int K, int n, int kbase, int t, int lo)
{
    float a0 = w[n * K + kbase + 2 * t];
    float a1 = w[n * K + kbase + 2 * t + 1];
    float a8 = w[n * K + kbase + 2 * t + 8];
    float a9 = w[n * K + kbase + 2 * t + 9];
    if (lo) {
        a0 -= __bfloat162float(__float2bfloat16(a0));
        a1 -= __bfloat162float(__float2bfloat16(a1));
        a8 -= __bfloat162float(__float2bfloat16(a8));
        a9 -= __bfloat162float(__float2bfloat16(a9));
    }
    uint2 r;
    r.x = packbf(a0, a1);
    r.y = packbf(a8, a9);
    return r;
}

__global__ void prep_kernel(
    const float* __restrict__ whh, const float* __restrict__ bih,
    const float* __restrict__ bhh, const float* __restrict__ pw,
    const float* __restrict__ w1,  const float* __restrict__ w2,
    const float* __restrict__ w3,
    const float* __restrict__ rw1, const float* __restrict__ rw2,
    const float* __restrict__ rw3)
{
    int gid = blockIdx.x * 128 + threadIdx.x;   // 4096 threads
    int nt  = gridDim.x * 128;
    for (int i = gid; i < 4096; i += nt) { int j = i >> 5, k = i & 31; g_whhT[k*128 + j] = whh[i]; }
    for (int i = gid; i < 512;  i += nt) { int m = i >> 5, k = i & 31; g_pwT [k*16  + m] = pw[i]; }
    for (int i = gid; i < 1024; i += nt) { int j = i >> 5, k = i & 31; g_w1T[k*32 + j] = w1[i];
                                           g_w2T[k*32 + j] = w2[i]; }
    for (int i = gid; i < 2048; i += nt) { int j = i >> 5, k = i & 31; g_w3T[k*64 + j] = w3[i]; }
    if (gid < 128) g_bsum[gid] = bih[gid] + bhh[gid];

    if (gid < 56 * 32) {
        int lane = gid & 31, fid = gid >> 5;
        int g = lane >> 2, t = lane & 3;
        uint2 f;
        if (fid < 32) {
            int lo = (fid >= 16);
            int c  = (fid & 15) >> 2, n4 = fid & 3;
            f = make_bfrag(rw1, 64, n4 * 8 + g, c * 16, t, lo);
        } else if (fid < 48) {
            int lo = (fid >= 40);
            int c  = ((fid - 32) & 7) >> 2, n4 = fid & 3;
            f = make_bfrag(rw2, 32, n4 * 8 + g, c * 16, t, lo);
        } else {
            int lo = (fid >= 52);
            int c  = ((fid - 48) & 3) >> 1, n2 = fid & 1;
            f = make_bfrag(rw3, 32, n2 * 8 + g, c * 16, t, lo);
        }
        g_frags[fid * 32 + lane] = f;
    }
}

// ---------------------------------------------------------------------------
// Kernel 1: reading MLP on tensor cores (bf16 3-term split, fp32 accum).
// Layer-1 input split streamed per k-chunk to cut register liveness.
// ---------------------------------------------------------------------------
__global__ void __launch_bounds__(256) mem_mlp_kernel(
    const float* __restrict__ x,
    const float* __restrict__ b1,
    const float* __restrict__ b2,
    const float* __restrict__ b3)
{
    __shared__ uint2 sW[56 * 32];
    __shared__ float sb1[32], sb2[32], sb3[16];

    int tid = threadIdx.x;
    #pragma unroll
    for (int i = 0; i < 7; i++) sW[tid + i * 256] = g_frags[tid + i * 256];
    if (tid < 32) { sb1[tid] = b1[tid]; sb2[tid] = b2[tid]; }
    if (tid < 16) sb3[tid] = b3[tid];
    __syncthreads();

    int lane = tid & 31, warp = tid >> 5;
    int g = lane >> 2, t = lane & 3;
    int wg = blockIdx.x * 8 + warp;          // 0..16383

    #pragma unroll 1
    for (int it = 0; it < 8; it++) {
        int tile = it * 16384 + wg;          // 0..131071
        const float* xr0 = x + ((size_t)tile * 16 + g) * 64;
        const float* xr1 = xr0 + 8 * 64;

        // prefetch all x (float2), consumed per-c below
        float2 x0[8], x1[8];
        #pragma unroll
        for (int c = 0; c < 4; c++) {
            x0[2*c]   = *(const float2*)(xr0 + c * 16 + 2 * t);
            x0[2*c+1] = *(const float2*)(xr0 + c * 16 + 2 * t + 8);
            x1[2*c]   = *(const float2*)(xr1 + c * 16 + 2 * t);
            x1[2*c+1] = *(const float2*)(xr1 + c * 16 + 2 * t + 8);
        }

        // ---- layer 1: K=64, N=32 (streaming split per k-chunk) ----
        float C1[4][4];
        #pragma unroll
        for (int n4 = 0; n4 < 4; n4++) {
            float q0 = sb1[n4 * 8 + 2 * t], q1 = sb1[n4 * 8 + 2 * t + 1];
            C1[n4][0] = q0; C1[n4][1] = q1; C1[n4][2] = q0; C1[n4][3] = q1;
        }
        #pragma unroll
        for (int c = 0; c < 4; c++) {
            unsigned int Ah[4], Al[4];
            split2(x0[2*c].x,   x0[2*c].y,   Ah[0], Al[0]);
            split2(x1[2*c].x,   x1[2*c].y,   Ah[1], Al[1]);
            split2(x0[2*c+1].x, x0[2*c+1].y, Ah[2], Al[2]);
            split2(x1[2*c+1].x, x1[2*c+1].y, Ah[3], Al[3]);
            #pragma unroll
            for (int n4 = 0; n4 < 4; n4++) {
                uint2 wh = sW[(c * 4 + n4) * 32 + lane];
                uint2 wl = sW[(16 + c * 4 + n4) * 32 + lane];
                mma16816(C1[n4], Ah, wh);
                mma16816(C1[n4], Al, wh);
                mma16816(C1[n4], Ah, wl);
            }
        }

        // ---- relu + split -> A2 ----
        unsigned int A2h[2][4], A2l[2][4];
        #pragma unroll
        for (int cc = 0; cc < 2; cc++) {
            #pragma unroll
            for (int h = 0; h < 2; h++) {
                float p0 = fmaxf(C1[2*cc][2*h],     0.f);
                float p1 = fmaxf(C1[2*cc][2*h + 1], 0.f);
                split2(p0, p1, A2h[cc][h], A2l[cc][h]);
                float q0 = fmaxf(C1[2*cc+1][2*h],     0.f);
                float q1 = fmaxf(C1[2*cc+1][2*h + 1], 0.f);
                split2(q0, q1, A2h[cc][2 + h], A2l[cc][2 + h]);
            }
        }

        // ---- layer 2: K=32, N=32 ----
        float C2[4][4];
        #pragma unroll
        for (int n4 = 0; n4 < 4; n4++) {
            float q0 = sb2[n4 * 8 + 2 * t], q1 = sb2[n4 * 8 + 2 * t + 1];
            C2[n4][0] = q0; C2[n4][1] = q1; C2[n4][2] = q0; C2[n4][3] = q1;
        }
        #pragma unroll
        for (int c = 0; c < 2; c++) {
            #pragma unroll
            for (int n4 = 0; n4 < 4; n4++) {
                uint2 wh = sW[(32 + c * 4 + n4) * 32 + lane];
                uint2 wl = sW[(40 + c * 4 + n4) * 32 + lane];
                mma16816(C2[n4], A2h[c], wh);
                mma16816(C2[n4], A2l[c], wh);
                mma16816(C2[n4], A2h[c], wl);
            }
        }

        // ---- relu + split -> A3 ----
        unsigned int A3h[2][4], A3l[2][4];
        #pragma unroll
        for (int cc = 0; cc < 2; cc++) {
            #pragma unroll
            for (int h = 0; h < 2; h++) {
                float p0 = fmaxf(C2[2*cc][2*h],     0.f);
                float p1 = fmaxf(C2[2*cc][2*h + 1], 0.f);
                split2(p0, p1, A3h[cc][h], A3l[cc][h]);
                float q0 = fmaxf(C2[2*cc+1][2*h],     0.f);
                float q1 = fmaxf(C2[2*cc+1][2*h + 1], 0.f);
                split2(q0, q1, A3h[cc][2 + h], A3l[cc][2 + h]);
            }
        }

        // ---- layer 3: K=32, N=16 (linear) ----
        float C3[2][4];
        #pragma unroll
        for (int n2 = 0; n2 < 2; n2++) {
            float q0 = sb3[n2 * 8 + 2 * t], q1 = sb3[n2 * 8 + 2 * t + 1];
            C3[n2][0] = q0; C3[n2][1] = q1; C3[n2][2] = q0; C3[n2][3] = q1;
        }
        #pragma unroll
        for (int c = 0; c < 2; c++) {
            #pragma unroll
            for (int n2 = 0; n2 < 2; n2++) {
                uint2 wh = sW[(48 + c * 2 + n2) * 32 + lane];
                uint2 wl = sW[(52 + c * 2 + n2) * 32 + lane];
                mma16816(C3[n2], A3h[c], wh);
                mma16816(C3[n2], A3l[c], wh);
                mma16816(C3[n2], A3h[c], wl);
            }
        }

        int R  = tile * 16;
        int b  = R >> 9;
        int s0 = (R & 511) + g;
        int s1 = s0 + 8;
        float* outb = g_memT + (size_t)b * 8192;
        #pragma unroll
        for (int n2 = 0; n2 < 2; n2++) {
            int m0 = n2 * 8 + 2 * t;
            outb[m0 * 512 + s0]       = C3[n2][0];
            outb[(m0 + 1) * 512 + s0] = C3[n2][1];
            outb[m0 * 512 + s1]       = C3[n2][2];
            outb[(m0 + 1) * 512 + s1] = C3[n2][3];
        }
    }
}

// ---------------------------------------------------------------------------
// Kernel 2 v3: 128 threads / 4 warps per batch. Memory tile lives in
// REGISTERS (16 float4 per lane, loaded coalesced from global — no smem
// staging). Small GEMVs computed redundantly per warp; only 2 barriers per
// step via double-buffered reduction scratch.
// ---------------------------------------------------------------------------
__device__ __forceinline__ float sigmoidf_(float x) {
    return 1.f / (1.f + __expf(-x));
}

__global__ void __launch_bounds__(128) step_kernel(
    const int*   __restrict__ lengths,
    const float* __restrict__ pb_,   // 16
    const float* __restrict__ b1,    // 32
    const float* __restrict__ b2,    // 32
    const float* __restrict__ b3,    // 64
    const float* __restrict__ esv_,  // 64
    float*       __restrict__ out)   // (B,64)
{
    __shared__ float red[2][72];   // [pb][0:4)=max, [4:8)=sum, [8:72)=r partials

    const unsigned FULL = 0xffffffffu;
    int b    = blockIdx.x;
    int tid  = threadIdx.x;
    int lane = tid & 31;
    int warp = tid >> 5;

    // ---- load this lane's 16 tile columns (s = 4*(lane+32*warp)+0..3) ----
    float4 v[16];
    {
        const float4* gm = (const float4*)(g_memT + (size_t)b * (MM * SS));
        int base = lane + 32 * warp;        // float4 column index, 0..127
        #pragma unroll
        for (int m = 0; m < 16; m++) v[m] = gm[m * 128 + base];
    }

    int len  = lengths[b];
    int slen = (len > 0) ? len : 1;
    int sbase = 4 * (lane + 32 * warp);

    // per-lane biases (redundant per warp)
    float bs0 = g_bsum[lane];
    float bs1 = g_bsum[32 + lane];
    float bs2 = g_bsum[64 + lane];
    float bs3 = g_bsum[96 + lane];
    float pbr = pb_[lane & 15];

    float qstar = 0.f;      // q_star[lane] (replicated per warp)
    float c     = 0.f;      // LSTM cell state[lane]
    int   pb    = 0;

    #pragma unroll 1
    for (int step = 0; step < NSTEPS; step++) {
        // ---- gates (redundant per warp): lane computes gates lane,+32,+64,+96
        float a0 = bs0, a1 = bs1, a2 = bs2, a3 = bs3;
        #pragma unroll
        for (int k = 0; k < 32; k++) {
            float qk = __shfl_sync(FULL, qstar, k);
            const float* wr = g_whhT + k * 128;
            a0 = fmaf(qk, __ldg(wr + lane),       a0);
            a1 = fmaf(qk, __ldg(wr + 32 + lane),  a1);
            a2 = fmaf(qk, __ldg(wr + 64 + lane),  a2);
            a3 = fmaf(qk, __ldg(wr + 96 + lane),  a3);
        }
        float ig = sigmoidf_(a0);
        float fg = sigmoidf_(a1);
        float gg = tanhf(a2);
        float og = sigmoidf_(a3);
        c = fmaf(fg, c, ig * gg);
        float h = og * tanhf(c);

        // ---- q = h @ proj_w.T + proj_b (redundant per warp) ----
        float aq = pbr;
        {
            int m = lane & 15;
            #pragma unroll
            for (int k = 0; k < 32; k++) {
                float hk = __shfl_sync(FULL, h, k);
                aq = fmaf(hk, __ldg(g_pwT + k * 16 + m), aq);
            }
        }
        float qm[16];
        #pragma unroll
        for (int m = 0; m < 16; m++) qm[m] = __shfl_sync(FULL, aq, m);

        // ---- e over this lane's 4 s-values ----
        float4 acc = make_float4(0.f, 0.f, 0.f, 0.f);
        #pragma unroll
        for (int m = 0; m < 16; m++) {
            float q = qm[m];
            acc.x = fmaf(q, v[m].x, acc.x);
            acc.y = fmaf(q, v[m].y, acc.y);
            acc.z = fmaf(q, v[m].z, acc.z);
            acc.w = fmaf(q, v[m].w, acc.w);
        }
        if (sbase     >= slen) acc.x = -1e30f;
        if (sbase + 1 >= slen) acc.y = -1e30f;
        if (sbase + 2 >= slen) acc.z = -1e30f;
        if (sbase + 3 >= slen) acc.w = -1e30f;

        // warp max -> red[pb][warp]
        float mx = fmaxf(fmaxf(acc.x, acc.y), fmaxf(acc.z, acc.w));
        #pragma unroll
        for (int off = 16; off; off >>= 1)
            mx = fmaxf(mx, __shfl_xor_sync(FULL, mx, off));
        if (lane == 0) red[pb][warp] = mx;
        __syncthreads();                          // barrier 1
        mx = fmaxf(fmaxf(red[pb][0], red[pb][1]),
                   fmaxf(red[pb][2], red[pb][3]));

        float4 ex;
        ex.x = __expf(acc.x - mx);
        ex.y = __expf(acc.y - mx);
        ex.z = __expf(acc.z - mx);
        ex.w = __expf(acc.w - mx);
        float ssum = (ex.x + ex.y) + (ex.z + ex.w);
        #pragma unroll
        for (int off = 16; off; off >>= 1)
            ssum += __shfl_xor_sync(FULL, ssum, off);

        // r partials over this warp's chunk
        float rm[16];
        #pragma unroll
        for (int m = 0; m < 16; m++)
            rm[m] = fmaf(ex.x, v[m].x,
                    fmaf(ex.y, v[m].y,
                    fmaf(ex.z, v[m].z, ex.w * v[m].w)));
        #pragma unroll
        for (int m = 0; m < 16; m++) {
            #pragma unroll
            for (int off = 16; off; off >>= 1)
                rm[m] += __shfl_xor_sync(FULL, rm[m], off);
        }
        if (lane == 0) {
            red[pb][4 + warp] = ssum;
            #pragma unroll
            for (int m = 0; m < 16; m++) red[pb][8 + warp * 16 + m] = rm[m];
        }
        __syncthreads();                          // barrier 2

        // ---- combine (redundant per warp, register-only result) ----
        float inv = 1.f / ((red[pb][4] + red[pb][5]) + (red[pb][6] + red[pb][7]));
        float nq;
        if (lane < 16) {
            nq = qm[lane];
        } else {
            int m = lane - 16;
            nq = ((red[pb][8 + m] + red[pb][24 + m]) +
                  (red[pb][40 + m] + red[pb][56 + m])) * inv;
        }
        qstar = nq;
        pb ^= 1;
    }

    // ---- write MLP on warp 0 (R5-style register GEMVs) ----
    if (warp != 0) return;

    float x1 = b1[lane];
    #pragma unroll
    for (int k = 0; k < 32; k++) {
        float qk = __shfl_sync(FULL, qstar, k);
        x1 = fmaf(qk, __ldg(g_w1T + k * 32 + lane), x1);
    }
    x1 = fmaxf(x1, 0.f);

    float x2 = b2[lane];
    #pragma unroll
    for (int k = 0; k < 32; k++) {
        float hk = __shfl_sync(FULL, x1, k);
        x2 = fmaf(hk, __ldg(g_w2T + k * 32 + lane), x2);
    }
    x2 = fmaxf(x2, 0.f);

    float o0 = b3[lane], o1 = b3[32 + lane];
    #pragma unroll
    for (int k = 0; k < 32; k++) {
        float hk = __shfl_sync(FULL, x2, k);
        o0 = fmaf(hk, __ldg(g_w3T + k * 64 + lane),      o0);
        o1 = fmaf(hk, __ldg(g_w3T + k * 64 + 32 + lane), o1);
    }
    float* op = out + (size_t)b * OUTD;
    op[lane]      = (len > 0) ? o0 : esv_[lane];
    op[32 + lane] = (len > 0) ? o1 : esv_[32 + lane];
}

// ---------------------------------------------------------------------------
extern "C" void kernel_launch(void* const* d_in, const int* in_sizes, int n_in,
                              void* d_out, int out_size)
{
    const float* input_set = (const float*)d_in[0];
    const int*   lengths   = (const int*)  d_in[1];
    const float* r_w1 = (const float*)d_in[2];
    const float* r_b1 = (const float*)d_in[3];
    const float* r_w2 = (const float*)d_in[4];
    const float* r_b2 = (const float*)d_in[5];
    const float* r_w3 = (const float*)d_in[6];
    const float* r_b3 = (const float*)d_in[7];
    // d_in[8] = lstm_wih (unused: LSTM input is identically zero)
    const float* lstm_whh = (const float*)d_in[9];
    const float* lstm_bih = (const float*)d_in[10];
    const float* lstm_bhh = (const float*)d_in[11];
    const float* proj_w   = (const float*)d_in[12];
    const float* proj_b   = (const float*)d_in[13];
    const float* w_w1 = (const float*)d_in[14];
    const float* w_b1 = (const float*)d_in[15];
    const float* w_w2 = (const float*)d_in[16];
    const float* w_b2 = (const float*)d_in[17];
    const float* w_w3 = (const float*)d_in[18];
    const float* w_b3 = (const float*)d_in[19];
    const float* esv  = (const float*)d_in[20];
    float* out = (float*)d_out;

    prep_kernel<<<32, 128>>>(lstm_whh, lstm_bih, lstm_bhh, proj_w,
                             w_w1, w_w2, w_w3,
                             r_w1, r_w2, r_w3);

    mem_mlp_kernel<<<2048, 256>>>(input_set, r_b1, r_b2, r_b3);

    step_kernel<<<BB, 128>>>(lengths, proj_b, w_b1, w_b2, w_b3, esv, out);
}